// round 10
// baseline (speedup 1.0000x reference)
#include <cuda_runtime.h>
#include <cuda_bf16.h>
#include <cuda_fp8.h>
#include <cstdint>

// Problem dims (fixed by the dataset)
#define T_DIM 8192
#define H_DIM 2048
#define I_DIM 8192

// ============================ device scratch ================================
__device__ __align__(16) unsigned char g_xq[(size_t)T_DIM * H_DIM];
__device__ __align__(16) unsigned char g_gq[(size_t)I_DIM * H_DIM];
__device__ __align__(16) unsigned char g_uq[(size_t)I_DIM * H_DIM];
__device__ __align__(16) unsigned char g_dq[(size_t)H_DIM * I_DIM];
__device__ __align__(16) __nv_bfloat16 g_inter[(size_t)T_DIM * I_DIM];
__device__ __align__(16) unsigned char g_iq[(size_t)T_DIM * I_DIM];
__device__ float g_amax[8];      // 0:x 1:gate_w 2:up_w 3:down_w 4:inter
__device__ float g_scale_q[8];   // 448/amax
__device__ float g_scale_dq[8];  // 1/(448/amax)

// ============================ helpers =======================================
__device__ __forceinline__ uint32_t smem_u32(const void* p) {
    return (uint32_t)__cvta_generic_to_shared(p);
}

__device__ __forceinline__ void cp_async16(uint32_t saddr, const void* gptr) {
    asm volatile("cp.async.cg.shared.global [%0], [%1], 16;" :: "r"(saddr), "l"(gptr));
}
__device__ __forceinline__ void cp_async_commit() {
    asm volatile("cp.async.commit_group;" ::: "memory");
}
template <int N>
__device__ __forceinline__ void cp_async_wait() {
    asm volatile("cp.async.wait_group %0;" :: "n"(N) : "memory");
}

__device__ __forceinline__ void ldsm_x4(uint32_t* r, uint32_t addr) {
    asm volatile("ldmatrix.sync.aligned.m8n8.x4.shared.b16 {%0,%1,%2,%3}, [%4];"
                 : "=r"(r[0]), "=r"(r[1]), "=r"(r[2]), "=r"(r[3]) : "r"(addr));
}

// 4 packed e4m3 bytes -> two f16x2 regs (lo = bytes 0,1; hi = bytes 2,3).
__device__ __forceinline__ void cvt8(uint32_t v, uint32_t& lo, uint32_t& hi) {
    asm("{\n\t"
        ".reg .b16 l, h;\n\t"
        "mov.b32 {l, h}, %2;\n\t"
        "cvt.rn.f16x2.e4m3x2 %0, l;\n\t"
        "cvt.rn.f16x2.e4m3x2 %1, h;\n\t"
        "}"
        : "=r"(lo), "=r"(hi) : "r"(v));
}

// f16 x f16 -> f32 MMA, m16n8k16
__device__ __forceinline__ void mma_f16(float* c, const uint32_t* a, const uint32_t* b) {
    asm volatile(
        "mma.sync.aligned.m16n8k16.row.col.f32.f16.f16.f32 "
        "{%0,%1,%2,%3}, {%4,%5,%6,%7}, {%8,%9}, {%0,%1,%2,%3};"
        : "+f"(c[0]), "+f"(c[1]), "+f"(c[2]), "+f"(c[3])
        : "r"(a[0]), "r"(a[1]), "r"(a[2]), "r"(a[3]), "r"(b[0]), "r"(b[1]));
}

__device__ __forceinline__ float bf16r(float x) {
    return __bfloat162float(__float2bfloat16(x));
}

// XLA's EmitFastTanh (Eigen-style rational polynomial) — the exact f32 tanh
// the reference's bf16 tanh upcasts into. Non-FMA Horner, clamp, small-x path.
__device__ __forceinline__ float xla_tanh_f32(float x) {
    const float kMax = 7.90531110763549805f;
    float xc = fminf(fmaxf(x, -kMax), kMax);
    float x2 = __fmul_rn(xc, xc);
    float np = -2.76076847742355e-16f;
    np = __fadd_rn(__fmul_rn(np, x2), 2.00018790482477e-13f);
    np = __fadd_rn(__fmul_rn(np, x2), -8.60467152213735e-11f);
    np = __fadd_rn(__fmul_rn(np, x2), 5.12229709037114e-08f);
    np = __fadd_rn(__fmul_rn(np, x2), 1.48572235717979e-05f);
    np = __fadd_rn(__fmul_rn(np, x2), 6.37261928875436e-04f);
    np = __fadd_rn(__fmul_rn(np, x2), 4.89352455891786e-03f);
    float numerator = __fmul_rn(xc, np);
    float dp = 1.19825839466702e-06f;
    dp = __fadd_rn(__fmul_rn(dp, x2), 1.18534705686654e-04f);
    dp = __fadd_rn(__fmul_rn(dp, x2), 2.26843463243900e-03f);
    dp = __fadd_rn(__fmul_rn(dp, x2), 4.89352518554385e-03f);
    float res = __fdiv_rn(numerator, dp);
    return (fabsf(x) < 0.0004f) ? x : res;
}

// Eager-mode jax.nn.gelu(approximate=True) on bf16: each HLO op rounds bf16.
// integer_pow(x,3) expands to TWO bf16-rounded multiplies (x2=x*x; x3=x2*x).
__device__ __forceinline__ float gelu_bf16_chain(float x /* bf16-valued */) {
    float x2 = bf16r(x * x);                  // integer_pow expansion, round 1
    float x3 = bf16r(x2 * x);                 // round 2
    float t1 = bf16r(0.044677734375f * x3);   // bf16(0.044715)
    float t2 = bf16r(x + t1);
    float t3 = bf16r(0.796875f * t2);         // bf16(sqrt(2/pi))
    float th = bf16r(xla_tanh_f32(t3));
    float t4 = bf16r(1.0f + th);
    float t5 = 0.5f * t4;                     // exact halving
    return bf16r(x * t5);
}

// ============================ small kernels =================================
__global__ void init_amax_kernel() {
    if (threadIdx.x < 8) g_amax[threadIdx.x] = 0.0f;
}

__global__ void amax_kernel(const float* __restrict__ src, int n4, int idx) {
    float m = 0.0f;
    const float4* s = (const float4*)src;
    for (int i = blockIdx.x * blockDim.x + threadIdx.x; i < n4;
         i += gridDim.x * blockDim.x) {
        float4 v = s[i];
        m = fmaxf(m, fmaxf(fmaxf(fabsf(v.x), fabsf(v.y)),
                           fmaxf(fabsf(v.z), fabsf(v.w))));
    }
    #pragma unroll
    for (int o = 16; o; o >>= 1) m = fmaxf(m, __shfl_xor_sync(0xffffffffu, m, o));
    if ((threadIdx.x & 31) == 0)
        atomicMax((unsigned int*)&g_amax[idx], __float_as_uint(m));
}

__global__ void compute_scales_kernel() {
    int i = threadIdx.x;
    if (i < 4) {
        float a = fmaxf(g_amax[i], 1e-12f);
        float s = 448.0f / a;
        g_scale_q[i] = s;
        g_scale_dq[i] = 1.0f / s;
    }
}

__global__ void quant_kernel(const float* __restrict__ src,
                             unsigned char* __restrict__ dst, int n4, int sidx) {
    float s = g_scale_q[sidx];
    const float4* s4 = (const float4*)src;
    uint32_t* d4 = (uint32_t*)dst;
    for (int i = blockIdx.x * blockDim.x + threadIdx.x; i < n4;
         i += gridDim.x * blockDim.x) {
        float4 v = s4[i];
        uint32_t b0 = __nv_cvt_float_to_fp8(v.x * s, __NV_SATFINITE, __NV_E4M3);
        uint32_t b1 = __nv_cvt_float_to_fp8(v.y * s, __NV_SATFINITE, __NV_E4M3);
        uint32_t b2 = __nv_cvt_float_to_fp8(v.z * s, __NV_SATFINITE, __NV_E4M3);
        uint32_t b3 = __nv_cvt_float_to_fp8(v.w * s, __NV_SATFINITE, __NV_E4M3);
        d4[i] = b0 | (b1 << 8) | (b2 << 16) | (b3 << 24);
    }
}

// inter (bf16) -> fp8 bytes; scale chain bf16-rounded (inter is bf16 tensor)
__global__ void quant_inter_kernel(int n8) {
    float amax4 = fmaxf(g_amax[4], 1e-12f);
    float s = bf16r(448.0f / amax4);
    const uint4* src = (const uint4*)g_inter;   // 8 bf16 per uint4
    uint2* dst = (uint2*)g_iq;
    for (int i = blockIdx.x * blockDim.x + threadIdx.x; i < n8;
         i += gridDim.x * blockDim.x) {
        uint4 v = src[i];
        uint32_t words[4] = {v.x, v.y, v.z, v.w};
        uint32_t out[2] = {0u, 0u};
        #pragma unroll
        for (int w = 0; w < 4; w++) {
            float f0 = __bfloat162float(__ushort_as_bfloat16((unsigned short)(words[w] & 0xffffu)));
            float f1 = __bfloat162float(__ushort_as_bfloat16((unsigned short)(words[w] >> 16)));
            uint32_t q0 = __nv_cvt_float_to_fp8(f0 * s, __NV_SATFINITE, __NV_E4M3);
            uint32_t q1 = __nv_cvt_float_to_fp8(f1 * s, __NV_SATFINITE, __NV_E4M3);
            out[w >> 1] |= (q0 | (q1 << 8)) << ((w & 1) * 16);
        }
        dst[i] = make_uint2(out[0], out[1]);
    }
}

// ============================ GEMM kernel ===================================
// CTA tile 128(M) x 128(N), K-chunk 128 bytes, 512 threads = 16 warps (4x4),
// warp tile 32x32. fp8 bytes in smem -> exact f16 via cvt -> m16n8k16 f32 mma.
//
// FUSED=true : A=xq, B0=gate_w_q, B1=up_w_q; epilogue bf16 GELU(gate)*up
//              -> g_inter (bf16) + inter amax.
// FUSED=false: single GEMM; epilogue scales, rounds to bf16, writes f32
//              (harness output dtype is float32 = widened bf16 values).

static constexpr int KCH    = 128;              // K bytes per chunk
static constexpr int STRIDE = 144;              // padded smem row stride
static constexpr int TILE   = 128 * STRIDE;     // 18432 B per tile

template <bool FUSED>
__global__ void __launch_bounds__(512, 1)
gemm_fp8_kernel(const unsigned char* __restrict__ A,
                const unsigned char* __restrict__ B0,
                const unsigned char* __restrict__ B1,
                void* __restrict__ out_v,
                int K, int ldo) {
    extern __shared__ __align__(16) char smem[];
    const uint32_t sb = smem_u32(smem);
    const int tid = threadIdx.x;
    const int wid = tid >> 5;
    const int lid = tid & 31;
    const int warp_m = (wid & 3) * 32;
    const int warp_n = (wid >> 2) * 32;
    const int m0 = blockIdx.x * 128;
    const int n0 = blockIdx.y * 128;

    const int NT = FUSED ? 3 : 2;       // tensors per buffer
    const int BUFSZ = NT * TILE;

    auto load_tile = [&](uint32_t sbase, const unsigned char* src, int row0,
                         int k0) {
        const char* base = (const char*)src + (size_t)row0 * K + k0;
        #pragma unroll
        for (int i = 0; i < 2; i++) {
            int c = tid + i * 512;
            int r = c >> 3;
            int s = (c & 7) << 4;
            cp_async16(sbase + r * STRIDE + s, base + (size_t)r * K + s);
        }
    };
    auto load_chunk = [&](int buf, int kc) {
        const uint32_t s0 = sb + buf * BUFSZ;
        const int k0 = kc * KCH;
        load_tile(s0, A, m0, k0);
        load_tile(s0 + TILE, B0, n0, k0);
        if (FUSED) load_tile(s0 + 2 * TILE, B1, n0, k0);
        cp_async_commit();
    };

    const int lr = lid & 7;
    const int lg = lid >> 3;
    const uint32_t a_lane = (uint32_t)((warp_m + lr + (lg & 1) * 8) * STRIDE +
                                       (lg >> 1) * 16);
    const uint32_t b_lane = (uint32_t)((warp_n + lr + (lg >> 1) * 8) * STRIDE +
                                       (lg & 1) * 16);

    float accg[2][4][4];
    float accu[FUSED ? 2 : 1][4][4];
    #pragma unroll
    for (int mt = 0; mt < 2; mt++)
        #pragma unroll
        for (int nt = 0; nt < 4; nt++)
            #pragma unroll
            for (int e = 0; e < 4; e++) {
                accg[mt][nt][e] = 0.0f;
                if (FUSED) accu[mt][nt][e] = 0.0f;
            }

    const int NCH = K / KCH;
    load_chunk(0, 0);

    for (int kc = 0; kc < NCH; ++kc) {
        const int buf = kc & 1;
        if (kc + 1 < NCH) {
            load_chunk(buf ^ 1, kc + 1);
            cp_async_wait<1>();
        } else {
            cp_async_wait<0>();
        }
        __syncthreads();

        const uint32_t sA  = sb + buf * BUFSZ;
        const uint32_t sBg = sA + TILE;
        const uint32_t sBu = sBg + TILE;

        #pragma unroll
        for (int ks = 0; ks < 4; ks++) {
            uint32_t af[2][4];
            #pragma unroll
            for (int mt = 0; mt < 2; mt++)
                ldsm_x4(af[mt], sA + a_lane + mt * 16 * STRIDE + ks * 32);
            uint32_t a16[2][2][4];   // [khalf][mt][4 regs]
            #pragma unroll
            for (int mt = 0; mt < 2; mt++) {
                cvt8(af[mt][0], a16[0][mt][0], a16[0][mt][2]);
                cvt8(af[mt][1], a16[0][mt][1], a16[0][mt][3]);
                cvt8(af[mt][2], a16[1][mt][0], a16[1][mt][2]);
                cvt8(af[mt][3], a16[1][mt][1], a16[1][mt][3]);
            }

            #pragma unroll
            for (int p = 0; p < 2; p++) {
                uint32_t bq[4];
                ldsm_x4(bq, sBg + b_lane + p * 16 * STRIDE + ks * 32);
                #pragma unroll
                for (int half = 0; half < 2; half++) {
                    uint32_t B0r[2], B1r[2];
                    cvt8(bq[2 * half],     B0r[0], B0r[1]);   // k 0-15
                    cvt8(bq[2 * half + 1], B1r[0], B1r[1]);   // k 16-31
                    const int nt = p * 2 + half;
                    #pragma unroll
                    for (int mt = 0; mt < 2; mt++) {
                        mma_f16(accg[mt][nt], a16[0][mt], B0r);
                        mma_f16(accg[mt][nt], a16[1][mt], B1r);
                    }
                }
            }
            if (FUSED) {
                #pragma unroll
                for (int p = 0; p < 2; p++) {
                    uint32_t bq[4];
                    ldsm_x4(bq, sBu + b_lane + p * 16 * STRIDE + ks * 32);
                    #pragma unroll
                    for (int half = 0; half < 2; half++) {
                        uint32_t B0r[2], B1r[2];
                        cvt8(bq[2 * half],     B0r[0], B0r[1]);
                        cvt8(bq[2 * half + 1], B1r[0], B1r[1]);
                        const int nt = p * 2 + half;
                        #pragma unroll
                        for (int mt = 0; mt < 2; mt++) {
                            mma_f16(accu[mt][nt], a16[0][mt], B0r);
                            mma_f16(accu[mt][nt], a16[1][mt], B1r);
                        }
                    }
                }
            }
        }
        __syncthreads();
    }

    // ---------------- epilogue ----------------
    const int rbase = m0 + warp_m + (lid >> 2);
    const int cbase = n0 + warp_n + (lid & 3) * 2;

    if (FUSED) {
        __nv_bfloat16* out = (__nv_bfloat16*)out_v;
        const float sA = g_scale_dq[0];
        const float fG = sA * g_scale_dq[1];
        const float fU = sA * g_scale_dq[2];
        float lamax = 0.0f;
        #pragma unroll
        for (int mt = 0; mt < 2; mt++) {
            #pragma unroll
            for (int nt = 0; nt < 4; nt++) {
                #pragma unroll
                for (int half = 0; half < 2; half++) {
                    const int row = rbase + mt * 16 + half * 8;
                    const int col = cbase + nt * 8;
                    uint32_t w = 0;
                    #pragma unroll
                    for (int e = 0; e < 2; e++) {
                        float gf = bf16r(accg[mt][nt][half * 2 + e] * fG);
                        float uf = bf16r(accu[mt][nt][half * 2 + e] * fU);
                        float pb = bf16r(gelu_bf16_chain(gf) * uf);
                        lamax = fmaxf(lamax, fabsf(pb));
                        w |= ((uint32_t)__bfloat16_as_ushort(__float2bfloat16(pb)))
                             << (e * 16);
                    }
                    *(uint32_t*)(out + (size_t)row * ldo + col) = w;
                }
            }
        }
        #pragma unroll
        for (int o = 16; o; o >>= 1)
            lamax = fmaxf(lamax, __shfl_xor_sync(0xffffffffu, lamax, o));
        if (lid == 0)
            atomicMax((unsigned int*)&g_amax[4], __float_as_uint(lamax));
    } else {
        // FINAL OUTPUT IS float32 (= bf16 values widened to f32)
        float* out = (float*)out_v;
        const float amax4 = fmaxf(g_amax[4], 1e-12f);
        const float s4 = bf16r(448.0f / amax4);       // bf16 scale
        const float f = bf16r(1.0f / s4) * g_scale_dq[3];
        #pragma unroll
        for (int mt = 0; mt < 2; mt++) {
            #pragma unroll
            for (int nt = 0; nt < 4; nt++) {
                #pragma unroll
                for (int half = 0; half < 2; half++) {
                    const int row = rbase + mt * 16 + half * 8;
                    const int col = cbase + nt * 8;
                    float2 w;
                    w.x = bf16r(accg[mt][nt][half * 2] * f);
                    w.y = bf16r(accg[mt][nt][half * 2 + 1] * f);
                    *(float2*)(out + (size_t)row * ldo + col) = w;
                }
            }
        }
    }
}

// ============================ launcher ======================================
extern "C" void kernel_launch(void* const* d_in, const int* in_sizes, int n_in,
                              void* d_out, int out_size) {
    const float* x  = (const float*)d_in[0];
    const float* gw = (const float*)d_in[1];
    const float* uw = (const float*)d_in[2];
    const float* dw = (const float*)d_in[3];

    void *p_xq, *p_gq, *p_uq, *p_dq, *p_inter, *p_iq;
    cudaGetSymbolAddress(&p_xq, g_xq);
    cudaGetSymbolAddress(&p_gq, g_gq);
    cudaGetSymbolAddress(&p_uq, g_uq);
    cudaGetSymbolAddress(&p_dq, g_dq);
    cudaGetSymbolAddress(&p_inter, g_inter);
    cudaGetSymbolAddress(&p_iq, g_iq);

    const int SMEM_FUSED = 2 * 3 * TILE;  // 110592
    const int SMEM_PLAIN = 2 * 2 * TILE;  // 73728
    cudaFuncSetAttribute(gemm_fp8_kernel<true>,
                         cudaFuncAttributeMaxDynamicSharedMemorySize, SMEM_FUSED);
    cudaFuncSetAttribute(gemm_fp8_kernel<false>,
                         cudaFuncAttributeMaxDynamicSharedMemorySize, SMEM_PLAIN);

    const int n4 = (T_DIM * H_DIM) / 4;  // each input tensor: 16.7M elems

    init_amax_kernel<<<1, 32>>>();
    amax_kernel<<<1024, 256>>>(x, n4, 0);
    amax_kernel<<<1024, 256>>>(gw, n4, 1);
    amax_kernel<<<1024, 256>>>(uw, n4, 2);
    amax_kernel<<<1024, 256>>>(dw, n4, 3);
    compute_scales_kernel<<<1, 32>>>();
    quant_kernel<<<2048, 256>>>(x, (unsigned char*)p_xq, n4, 0);
    quant_kernel<<<2048, 256>>>(gw, (unsigned char*)p_gq, n4, 1);
    quant_kernel<<<2048, 256>>>(uw, (unsigned char*)p_uq, n4, 2);
    quant_kernel<<<2048, 256>>>(dw, (unsigned char*)p_dq, n4, 3);

    // GEMM1 fused: inter[T, I] = gelu(xq@gq^T * sxg) * (xq@uq^T * sxu) + amax
    gemm_fp8_kernel<true><<<dim3(T_DIM / 128, I_DIM / 128), 512, SMEM_FUSED>>>(
        (const unsigned char*)p_xq, (const unsigned char*)p_gq,
        (const unsigned char*)p_uq, p_inter, H_DIM, I_DIM);

    quant_inter_kernel<<<4096, 256>>>((int)(((size_t)T_DIM * I_DIM) / 8));

    // GEMM2: out_f32[T, H] = widen_bf16((iq @ dq^T) * (i_s*d_s))
    gemm_fp8_kernel<false><<<dim3(T_DIM / 128, H_DIM / 128), 512, SMEM_PLAIN>>>(
        (const unsigned char*)p_iq, (const unsigned char*)p_dq,
        nullptr, d_out, I_DIM, H_DIM);
}